// round 1
// baseline (speedup 1.0000x reference)
#include <cuda_runtime.h>

#define NB    8
#define NC    512
#define NL    2048
#define NH    8
#define ND    64
#define NHID  512
#define NOQKV 1536

// Scratch (device globals — allocation-free per harness rules)
__device__ float g_qkv[(size_t)NB * NOQKV * NL];   // [b][1536][2048]
__device__ float g_att[(size_t)NB * NHID * NL];    // [b][512][2048] attention output, channel-major

// ---------------------------------------------------------------------------
// Tiled fp32 GEMM:  Y[b][m][l] = sum_c W[m][c] * X[b][c][l]  (+ bias[m])
// 64x64 block tile, K-tile 16, 256 threads, 4x4 microtile per thread.
// ---------------------------------------------------------------------------
template<int M, int K, bool HAS_BIAS>
__global__ __launch_bounds__(256) void gemm_kernel(
    const float* __restrict__ W, const float* __restrict__ X,
    const float* __restrict__ bias, float* __restrict__ Y)
{
    __shared__ float As[16][68];   // [kk][m]
    __shared__ float Bs[16][68];   // [kk][n]

    const int b  = blockIdx.z;
    const int m0 = blockIdx.y * 64;
    const int n0 = blockIdx.x * 64;
    const float* Xb = X + (size_t)b * K * NL;
    float*       Yb = Y + (size_t)b * M * NL;

    const int tid = threadIdx.x;
    const int tx  = tid & 15;      // n microtile
    const int ty  = tid >> 4;      // m microtile

    float acc[4][4] = {};

    for (int k0 = 0; k0 < K; k0 += 16) {
        // A tile: each thread loads one float4 of a W row
        {
            int m  = tid >> 2;             // 0..63
            int kq = (tid & 3) * 4;        // 0,4,8,12
            float4 w4 = *(const float4*)&W[(size_t)(m0 + m) * K + k0 + kq];
            As[kq + 0][m] = w4.x;
            As[kq + 1][m] = w4.y;
            As[kq + 2][m] = w4.z;
            As[kq + 3][m] = w4.w;
        }
        // B tile: one float4 per thread, coalesced along l
        {
            int kk = tid >> 4;             // 0..15
            int nq = (tid & 15) * 4;       // 0..60
            *(float4*)&Bs[kk][nq] =
                *(const float4*)&Xb[(size_t)(k0 + kk) * NL + n0 + nq];
        }
        __syncthreads();

        #pragma unroll
        for (int kk = 0; kk < 16; kk++) {
            float4 a  = *(const float4*)&As[kk][ty * 4];
            float4 bv = *(const float4*)&Bs[kk][tx * 4];
            float av[4] = {a.x, a.y, a.z, a.w};
            float bb[4] = {bv.x, bv.y, bv.z, bv.w};
            #pragma unroll
            for (int r = 0; r < 4; r++)
                #pragma unroll
                for (int c = 0; c < 4; c++)
                    acc[r][c] += av[r] * bb[c];
        }
        __syncthreads();
    }

    #pragma unroll
    for (int r = 0; r < 4; r++) {
        int m = m0 + ty * 4 + r;
        float bval = HAS_BIAS ? bias[m] : 0.0f;
        float4 o4 = make_float4(acc[r][0] + bval, acc[r][1] + bval,
                                acc[r][2] + bval, acc[r][3] + bval);
        *(float4*)&Yb[(size_t)m * NL + n0 + tx * 4] = o4;
    }
}

// ---------------------------------------------------------------------------
// Flash attention: one CTA = 64 queries of one (b,h). BN=64 key tile.
// q,k,v stored [d][l] in g_qkv. Output written [d][l] into g_att channels.
// Online softmax in base-2 with scale*log2(e) folded in.
// ---------------------------------------------------------------------------
__global__ __launch_bounds__(256) void attn_kernel(
    const float* __restrict__ qkv, float* __restrict__ att)
{
    extern __shared__ float sm[];
    float (*qs)[68]  = (float(*)[68])sm;   // [d][i]
    float (*ks)[68]  = qs + 64;            // [d][j]
    float (*vts)[68] = ks + 64;            // [j][d]
    float (*ps)[68]  = vts + 64;           // [j][i]

    const int i0 = blockIdx.x * 64;
    const int h  = blockIdx.y;
    const int b  = blockIdx.z;
    const float* qp = qkv + ((size_t)b * NOQKV + h * ND) * NL;
    const float* kp = qp + (size_t)NHID * NL;
    const float* vp = qp + (size_t)2 * NHID * NL;

    const int tid = threadIdx.x;
    const int tx  = tid & 15;    // j (S phase) / d (O phase) microtile
    const int ty  = tid >> 4;    // i microtile

    // Load Q tile
    #pragma unroll
    for (int t = 0; t < 16; t++) {
        int idx = tid + t * 256;
        int i = idx & 63, d = idx >> 6;
        qs[d][i] = qp[(size_t)d * NL + i0 + i];
    }
    __syncthreads();

    float m_r[4], l_r[4], o[4][4];
    #pragma unroll
    for (int r = 0; r < 4; r++) {
        m_r[r] = -1e30f; l_r[r] = 0.0f;
        #pragma unroll
        for (int c = 0; c < 4; c++) o[r][c] = 0.0f;
    }

    const float SC = 0.125f * 1.44269504f;   // dim_head^-0.5 * log2(e)

    for (int j0 = 0; j0 < NL; j0 += 64) {
        // Load K tile [d][j] and V tile transposed [j][d]
        #pragma unroll
        for (int t = 0; t < 16; t++) {
            int idx = tid + t * 256;
            int j = idx & 63, d = idx >> 6;
            ks[d][j]  = kp[(size_t)d * NL + j0 + j];
            vts[j][d] = vp[(size_t)d * NL + j0 + j];
        }
        __syncthreads();

        // S = Q^T K  (thread: rows i0t=ty*4.., cols j0t=tx*4..)
        float s[4][4] = {};
        #pragma unroll 8
        for (int d = 0; d < 64; d++) {
            float4 a  = *(const float4*)&qs[d][ty * 4];
            float4 bv = *(const float4*)&ks[d][tx * 4];
            s[0][0] += a.x * bv.x; s[0][1] += a.x * bv.y; s[0][2] += a.x * bv.z; s[0][3] += a.x * bv.w;
            s[1][0] += a.y * bv.x; s[1][1] += a.y * bv.y; s[1][2] += a.y * bv.z; s[1][3] += a.y * bv.w;
            s[2][0] += a.z * bv.x; s[2][1] += a.z * bv.y; s[2][2] += a.z * bv.z; s[2][3] += a.z * bv.w;
            s[3][0] += a.w * bv.x; s[3][1] += a.w * bv.y; s[3][2] += a.w * bv.z; s[3][3] += a.w * bv.w;
        }

        // Online softmax per row (row spread over the 16 tx lanes)
        #pragma unroll
        for (int r = 0; r < 4; r++) {
            float s0 = s[r][0] * SC, s1 = s[r][1] * SC;
            float s2 = s[r][2] * SC, s3 = s[r][3] * SC;
            float mx = fmaxf(fmaxf(s0, s1), fmaxf(s2, s3));
            mx = fmaxf(mx, __shfl_xor_sync(0xffffffffu, mx, 1));
            mx = fmaxf(mx, __shfl_xor_sync(0xffffffffu, mx, 2));
            mx = fmaxf(mx, __shfl_xor_sync(0xffffffffu, mx, 4));
            mx = fmaxf(mx, __shfl_xor_sync(0xffffffffu, mx, 8));
            float mnew = fmaxf(m_r[r], mx);
            float corr = exp2f(m_r[r] - mnew);
            float p0 = exp2f(s0 - mnew), p1 = exp2f(s1 - mnew);
            float p2 = exp2f(s2 - mnew), p3 = exp2f(s3 - mnew);
            l_r[r] = l_r[r] * corr + (p0 + p1 + p2 + p3);
            m_r[r] = mnew;
            o[r][0] *= corr; o[r][1] *= corr; o[r][2] *= corr; o[r][3] *= corr;
            ps[tx * 4 + 0][ty * 4 + r] = p0;
            ps[tx * 4 + 1][ty * 4 + r] = p1;
            ps[tx * 4 + 2][ty * 4 + r] = p2;
            ps[tx * 4 + 3][ty * 4 + r] = p3;
        }
        __syncthreads();

        // O += P * V   (thread: rows i=ty*4.., cols d=tx*4..)
        #pragma unroll 8
        for (int j = 0; j < 64; j++) {
            float4 pv = *(const float4*)&ps[j][ty * 4];
            float4 vv = *(const float4*)&vts[j][tx * 4];
            o[0][0] += pv.x * vv.x; o[0][1] += pv.x * vv.y; o[0][2] += pv.x * vv.z; o[0][3] += pv.x * vv.w;
            o[1][0] += pv.y * vv.x; o[1][1] += pv.y * vv.y; o[1][2] += pv.y * vv.z; o[1][3] += pv.y * vv.w;
            o[2][0] += pv.z * vv.x; o[2][1] += pv.z * vv.y; o[2][2] += pv.z * vv.z; o[2][3] += pv.z * vv.w;
            o[3][0] += pv.w * vv.x; o[3][1] += pv.w * vv.y; o[3][2] += pv.w * vv.z; o[3][3] += pv.w * vv.w;
        }
        __syncthreads();
    }

    // Finalize: full row denominator across tx lanes, normalize
    #pragma unroll
    for (int r = 0; r < 4; r++) {
        float lf = l_r[r];
        lf += __shfl_xor_sync(0xffffffffu, lf, 1);
        lf += __shfl_xor_sync(0xffffffffu, lf, 2);
        lf += __shfl_xor_sync(0xffffffffu, lf, 4);
        lf += __shfl_xor_sync(0xffffffffu, lf, 8);
        float inv = __fdividef(1.0f, lf);
        o[r][0] *= inv; o[r][1] *= inv; o[r][2] *= inv; o[r][3] *= inv;
    }

    // Transpose o[i][d] -> [d][i] via smem (reuse qs), write coalesced
    __syncthreads();
    #pragma unroll
    for (int r = 0; r < 4; r++)
        #pragma unroll
        for (int c = 0; c < 4; c++)
            qs[tx * 4 + c][ty * 4 + r] = o[r][c];
    __syncthreads();

    float* ap = att + ((size_t)b * NHID + h * ND) * NL + i0;
    #pragma unroll
    for (int t = 0; t < 16; t++) {
        int idx = tid + t * 256;
        int i = idx & 63, d = idx >> 6;
        ap[(size_t)d * NL + i] = qs[d][i];
    }
}

// ---------------------------------------------------------------------------
extern "C" void kernel_launch(void* const* d_in, const int* in_sizes, int n_in,
                              void* d_out, int out_size)
{
    const float* x     = (const float*)d_in[0];   // [8,512,2048]
    const float* w_qkv = (const float*)d_in[1];   // [1536,512]
    const float* w_out = (const float*)d_in[2];   // [512,512]
    const float* b_out = (const float*)d_in[3];   // [512]
    float* out = (float*)d_out;                   // [8,512,2048]

    float *qkv, *att;
    cudaGetSymbolAddress((void**)&qkv, g_qkv);
    cudaGetSymbolAddress((void**)&att, g_att);

    // 1) QKV projection
    gemm_kernel<NOQKV, NC, false>
        <<<dim3(NL / 64, NOQKV / 64, NB), 256>>>(w_qkv, x, nullptr, qkv);

    // 2) Attention
    int smem = 4 * 64 * 68 * (int)sizeof(float);  // 69632 B
    cudaFuncSetAttribute(attn_kernel,
                         cudaFuncAttributeMaxDynamicSharedMemorySize, smem);
    attn_kernel<<<dim3(NL / 64, NH, NB), 256, smem>>>(qkv, att);

    // 3) Output projection + bias
    gemm_kernel<NC, NHID, true>
        <<<dim3(NL / 64, NC / 64, NB), 256>>>(w_out, att, b_out, out);
}